// round 11
// baseline (speedup 1.0000x reference)
#include <cuda_runtime.h>
#include <cuda_bf16.h>
#include <math.h>
#include <stdint.h>

#define NN   8192
#define DD   200
#define BB   4
#define EE   4096
#define DEG  16
#define HH   128
#define EPSf 1e-8f
#define MAXDEG 64

// ---------------- scratch (device globals; no allocation allowed) ----------------
__device__ float g_y[NN * HH];        // x @ Wg
__device__ float g_Medge[EE * HH];
__device__ float g_gp[NN * HH];
__device__ float g_fused[NN * HH];
__device__ float g_Wg[DD * HH];       // W @ gnn_w
__device__ float g_bg[HH];            // b @ gnn_w + gnn_b
__device__ int   g_dv_cnt[NN];        // degree AND list cursor
__device__ int   g_de_cnt[EE];
__device__ unsigned g_maskbits[EE];
__device__ int   g_node_edges[NN * MAXDEG];
__device__ float g_alpha_part[256];
__device__ float g_alpha;
__device__ float g_att[BB * HH];
__device__ float g_cvec[BB * HH];

// ---------------- init: zero degree counters + alpha partial sums ----------------
__global__ void k_init(const float* __restrict__ x, const float* __restrict__ gw) {
    __shared__ float sm[256];
    int t = threadIdx.x;
    int gi = blockIdx.x * 256 + t;
    if (gi < NN) g_dv_cnt[gi] = 0;
    float s = 0.f;
    for (int i = gi; i < NN * DD; i += 256 * 256)
        s += x[i] * gw[i % DD];
    sm[t] = s; __syncthreads();
    for (int o = 128; o > 0; o >>= 1) { if (t < o) sm[t] += sm[t + o]; __syncthreads(); }
    if (t == 0) g_alpha_part[blockIdx.x] = sm[0];
}

__global__ void k_alpha_fin(const float* __restrict__ gb) {
    __shared__ float sm[256];
    int t = threadIdx.x;
    sm[t] = g_alpha_part[t]; __syncthreads();
    for (int o = 128; o > 0; o >>= 1) { if (t < o) sm[t] += sm[t + o]; __syncthreads(); }
    if (t == 0) g_alpha = 1.f / (1.f + expf(-(sm[0] / (float)NN + gb[0])));
}

// ---------------- Wg = W @ gnn_w ; bg = b @ gnn_w + gnn_b ----------------
__global__ void __launch_bounds__(256) k_prec(
        const float* __restrict__ W, const float* __restrict__ gnn_w,
        const float* __restrict__ gnn_b, const float* __restrict__ bvec) {
    __shared__ float rowv[16][DD + 1];
    const int r0 = blockIdx.x * 16;
    const int tid = threadIdx.x;
    const int col = tid & 127;
    const int rg  = tid >> 7;
    for (int i = tid; i < 16 * DD; i += 256) {
        int rr = i / DD, kk = i % DD;
        int row = r0 + rr;
        float v = 0.f;
        if (row < DD)        v = W[(size_t)row * DD + kk];
        else if (row == DD)  v = bvec[kk];
        rowv[rr][kk] = v;
    }
    __syncthreads();
    float s[8];
#pragma unroll
    for (int i = 0; i < 8; i++) s[i] = 0.f;
#pragma unroll 4
    for (int k = 0; k < DD; k++) {
        float w = gnn_w[k * HH + col];
#pragma unroll
        for (int i = 0; i < 8; i++) s[i] += rowv[rg * 8 + i][k] * w;
    }
#pragma unroll
    for (int i = 0; i < 8; i++) {
        int row = r0 + rg * 8 + i;
        if (row < DD)       g_Wg[row * HH + col] = s[i];
        else if (row == DD) g_bg[col] = s[i] + gnn_b[col];
    }
}

// ---------------- edge pass: slot-parallel dedup + degree + list fill ----------------
__global__ void __launch_bounds__(256) k_edge_a(const int* __restrict__ en) {
    const int gt   = blockIdx.x * 256 + threadIdx.x;   // 0 .. EE*DEG-1
    const int lane = threadIdx.x & 31;
    const int half = lane >> 4;
    const int s    = lane & 15;
    const int e    = (gt >> 5) * 2 + half;
    const int nd   = en[e * DEG + s];
    bool first = true;
#pragma unroll
    for (int j = 0; j < 15; j++) {
        int v = __shfl_sync(0xFFFFFFFFu, nd, (half << 4) + j);
        if (j < s && v == nd) first = false;
    }
    unsigned bal = __ballot_sync(0xFFFFFFFFu, first);
    unsigned m = (bal >> (half * 16)) & 0xFFFFu;
    if (s == 0) { g_maskbits[e] = m; g_de_cnt[e] = __popc(m); }
    if (first) {
        int p = atomicAdd(&g_dv_cnt[nd], 1);
        if (p < MAXDEG) g_node_edges[nd * MAXDEG + p] = e;
    }
}

// sort each node's edge list for deterministic FP order
__global__ void k_sort() {
    int n = blockIdx.x * blockDim.x + threadIdx.x;
    if (n >= NN) return;
    int len = g_dv_cnt[n]; if (len > MAXDEG) len = MAXDEG;
    int* a = &g_node_edges[n * MAXDEG];
    for (int i = 1; i < len; i++) {
        int key = a[i]; int j = i - 1;
        while (j >= 0 && a[j] > key) { a[j + 1] = a[j]; j--; }
        a[j + 1] = key;
    }
}

// Medge[e,:] over y (128 cols); 4 edges/block, 32 lanes/edge
__global__ void __launch_bounds__(128) k_edge_b(const int* __restrict__ en) {
    __shared__ int   sn[4][DEG];
    __shared__ float sw[4][DEG];
    const int tid = threadIdx.x;
    const int sub = tid >> 5, lane = tid & 31;
    const int e0 = blockIdx.x * 4;
    if (tid < 64) {
        int ee = tid >> 4, s = tid & 15;
        int e = e0 + ee;
        int n = en[e * DEG + s];
        sn[ee][s] = n;
        sw[ee][s] = ((g_maskbits[e] >> s) & 1u)
                      ? rsqrtf((float)g_dv_cnt[n] * (1.f / DEG) + EPSf) : 0.f;
    }
    __syncthreads();
    const int e = e0 + sub;
    float4 acc = make_float4(0.f, 0.f, 0.f, 0.f);
#pragma unroll
    for (int s = 0; s < DEG; s++) {
        float w = sw[sub][s];
        float4 v = ((const float4*)&g_y[(size_t)sn[sub][s] * HH])[lane];
        acc.x += w * v.x; acc.y += w * v.y; acc.z += w * v.z; acc.w += w * v.w;
    }
    float sc = 1.f / ((float)g_de_cnt[e] * (1.f / DEG) + EPSf) * (1.f / (DEG * DEG));
    ((float4*)&g_Medge[(size_t)e * HH])[lane] =
        make_float4(acc.x * sc, acc.y * sc, acc.z * sc, acc.w * sc);
}

// gp = alpha*y + (1-alpha)*dv*sum Medge + bg ; 8 nodes/block (warp per node)
__global__ void __launch_bounds__(256) k_gather() {
    const int n = blockIdx.x * 8 + (threadIdx.x >> 5);
    const int lane = threadIdx.x & 31;
    int len  = g_dv_cnt[n]; if (len > MAXDEG) len = MAXDEG;
    const int base = n * MAXDEG;
    const float dvn = rsqrtf((float)g_dv_cnt[n] * (1.f / DEG) + EPSf);
    const float alpha = g_alpha, beta = 1.f - alpha;
    float4 acc = make_float4(0.f, 0.f, 0.f, 0.f);
    for (int i = 0; i < len; i++) {
        int e = g_node_edges[base + i];
        float4 v = ((const float4*)&g_Medge[(size_t)e * HH])[lane];
        acc.x += v.x; acc.y += v.y; acc.z += v.z; acc.w += v.w;
    }
    float4 yv = ((const float4*)&g_y[(size_t)n * HH])[lane];
    float4 bg = ((const float4*)g_bg)[lane];
    ((float4*)&g_gp[(size_t)n * HH])[lane] =
        make_float4(alpha * yv.x + beta * dvn * acc.x + bg.x,
                    alpha * yv.y + beta * dvn * acc.y + bg.y,
                    alpha * yv.z + beta * dvn * acc.z + bg.z,
                    alpha * yv.w + beta * dvn * acc.w + bg.w);
}

// ---------------- per-batch constants (one block per batch) ----------------
__global__ void k_const(const float* __restrict__ text,
                        const float* __restrict__ text_w, const float* __restrict__ text_b,
                        const float* __restrict__ in_w,   const float* __restrict__ in_b,
                        const float* __restrict__ aow,    const float* __restrict__ aob,
                        const float* __restrict__ fgw,    const float* __restrict__ fgb) {
    __shared__ float tp[HH];
    __shared__ float vv[HH];
    __shared__ float at[HH];
    int b = blockIdx.x;
    int j = threadIdx.x;  // 128 threads
    {
        float s = text_b[j];
        for (int k = 0; k < DD; k++) s += text[b * DD + k] * text_w[k * HH + j];
        tp[j] = s;
    }
    __syncthreads();
    {
        float s = in_b[2 * HH + j];
        for (int k = 0; k < HH; k++) s += tp[k] * in_w[k * 3 * HH + 2 * HH + j];
        vv[j] = s;
    }
    __syncthreads();
    {
        float s = aob[j];
        for (int k = 0; k < HH; k++) s += vv[k] * aow[k * HH + j];
        at[j] = s;
        g_att[b * HH + j] = s;
    }
    __syncthreads();
    {
        float s = fgb[j];
        for (int k = 0; k < HH; k++) s += at[k] * fgw[(HH + k) * HH + j];
        g_cvec[b * HH + j] = s;
    }
}

// ---------------- tensor-core GEMM: double-buffered, packed hi/lo smem ----------------
__device__ __forceinline__ void mma_bf16(float* c, uint32_t a0, uint32_t a1,
                                         uint32_t a2, uint32_t a3,
                                         uint32_t b0, uint32_t b1) {
    asm volatile("mma.sync.aligned.m16n8k16.row.col.f32.bf16.bf16.f32 "
        "{%0,%1,%2,%3}, {%4,%5,%6,%7}, {%8,%9}, {%0,%1,%2,%3};"
        : "+f"(c[0]), "+f"(c[1]), "+f"(c[2]), "+f"(c[3])
        : "r"(a0), "r"(a1), "r"(a2), "r"(a3), "r"(b0), "r"(b1));
}
__device__ __forceinline__ void split2(float v0, float v1, uint32_t& hi, uint32_t& lo) {
    __nv_bfloat16 h0 = __float2bfloat16(v0), h1 = __float2bfloat16(v1);
    float l0 = v0 - __bfloat162float(h0);
    float l1 = v1 - __bfloat162float(h1);
    hi = (uint32_t)__bfloat16_as_ushort(h0) | ((uint32_t)__bfloat16_as_ushort(h1) << 16);
    lo = (uint32_t)__bfloat16_as_ushort(__float2bfloat16(l0))
       | ((uint32_t)__bfloat16_as_ushort(__float2bfloat16(l1)) << 16);
}

#define PST 40                 // u32 row stride
#define STG2 (192 * PST)       // u32 per stage
#define SMEM_BYTES (2 * STG2 * 4)

template <int MODE>
__global__ void __launch_bounds__(256)
tgemm(const float* __restrict__ Aext, const float* __restrict__ Bext,
      float* __restrict__ Cext, const float* __restrict__ bias) {
    constexpr int NCOLS = (MODE == 3) ? 200 : 128;
    constexpr int K     = (MODE == 1) ? 200 : 128;
    constexpr int LDA   = (MODE == 1) ? 200 : 128;
    constexpr int NCH   = (K + 31) / 32;

    extern __shared__ uint32_t sm[];

    const float* A = (MODE == 1) ? Aext
                   : (MODE == 2) ? (const float*)g_gp : (const float*)g_fused;
    const float* Bsrc = (MODE == 1) ? (const float*)g_Wg : Bext;
    float* C = (MODE == 1) ? (float*)g_y
             : (MODE == 2) ? (float*)g_fused : Cext;

    const int tid = threadIdx.x;
    const int lane = tid & 31;
    const int w = tid >> 5;
    const int wm = w & 3, wn = w >> 2;
    const int g = lane >> 2, tig = lane & 3;
    const int m0 = blockIdx.y * 128, n0 = blockIdx.x * 64;

    const int a_row = tid >> 3, a_kq = (tid & 7) * 4;
    const int b_m = tid & 15, b_nq = (tid >> 4) * 4;

    float acc[2][4][4];
#pragma unroll
    for (int mt = 0; mt < 2; mt++)
#pragma unroll
        for (int nt = 0; nt < 4; nt++)
#pragma unroll
            for (int j = 0; j < 4; j++) acc[mt][nt][j] = 0.f;

    const float4 z4 = make_float4(0.f, 0.f, 0.f, 0.f);
    float4 ar[4];
    float4 br0, br1;

    auto load_raw = [&](int k0) {
#pragma unroll
        for (int i = 0; i < 4; i++) {
            int row = a_row + i * 32;
            int gk = k0 + a_kq;
            ar[i] = (gk < K) ? *(const float4*)&A[(size_t)(m0 + row) * LDA + gk] : z4;
        }
        int gk0 = k0 + 2 * b_m, gk1 = gk0 + 1, gn = n0 + b_nq;
        br0 = (gk0 < K && gn < NCOLS) ? *(const float4*)&Bsrc[(size_t)gk0 * NCOLS + gn] : z4;
        br1 = (gk1 < K && gn < NCOLS) ? *(const float4*)&Bsrc[(size_t)gk1 * NCOLS + gn] : z4;
    };
    auto store_smem = [&](int buf) {
        uint32_t* Ap = sm + buf * STG2;
        uint32_t* Bp = Ap + 128 * PST;
#pragma unroll
        for (int i = 0; i < 4; i++) {
            int row = a_row + i * 32;
            uint32_t h0, l0, h1, l1;
            split2(ar[i].x, ar[i].y, h0, l0);
            split2(ar[i].z, ar[i].w, h1, l1);
            uint32_t* p = Ap + row * PST + a_kq;
            p[0] = h0; p[1] = l0; p[2] = h1; p[3] = l1;
        }
        float b0e[4] = {br0.x, br0.y, br0.z, br0.w};
        float b1e[4] = {br1.x, br1.y, br1.z, br1.w};
#pragma unroll
        for (int q = 0; q < 4; q++) {
            uint32_t hi, lo;
            split2(b0e[q], b1e[q], hi, lo);
            uint32_t* p = Bp + (b_nq + q) * PST + 2 * b_m;
            p[0] = hi; p[1] = lo;
        }
    };

    load_raw(0);
    store_smem(0);
    __syncthreads();

    for (int ch = 0; ch < NCH; ch++) {
        const int buf = ch & 1;
        const uint32_t* Ap = sm + buf * STG2;
        const uint32_t* Bp = Ap + 128 * PST;
        if (ch + 1 < NCH) load_raw((ch + 1) * 32);
#pragma unroll
        for (int ks = 0; ks < 32; ks += 16) {
            uint32_t ah[2][4], al[2][4];
#pragma unroll
            for (int mt = 0; mt < 2; mt++) {
                int r = wm * 32 + mt * 16 + g;
                uint2 p0 = *(const uint2*)(Ap + r * PST + ks + tig * 2);
                uint2 p1 = *(const uint2*)(Ap + (r + 8) * PST + ks + tig * 2);
                uint2 p2 = *(const uint2*)(Ap + r * PST + ks + tig * 2 + 8);
                uint2 p3 = *(const uint2*)(Ap + (r + 8) * PST + ks + tig * 2 + 8);
                ah[mt][0] = p0.x; al[mt][0] = p0.y;
                ah[mt][1] = p1.x; al[mt][1] = p1.y;
                ah[mt][2] = p2.x; al[mt][2] = p2.y;
                ah[mt][3] = p3.x; al[mt][3] = p3.y;
            }
            uint32_t bh[4][2], bl[4][2];
#pragma unroll
            for (int nt = 0; nt < 4; nt++) {
                int n = wn * 32 + nt * 8 + g;
                uint2 q0 = *(const uint2*)(Bp + n * PST + ks + tig * 2);
                uint2 q1 = *(const uint2*)(Bp + n * PST + ks + tig * 2 + 8);
                bh[nt][0] = q0.x; bl[nt][0] = q0.y;
                bh[nt][1] = q1.x; bl[nt][1] = q1.y;
            }
#pragma unroll
            for (int mt = 0; mt < 2; mt++)
#pragma unroll
                for (int nt = 0; nt < 4; nt++) {
                    mma_bf16(acc[mt][nt], ah[mt][0], ah[mt][1], ah[mt][2], ah[mt][3],
                             bh[nt][0], bh[nt][1]);
                    mma_bf16(acc[mt][nt], al[mt][0], al[mt][1], al[mt][2], al[mt][3],
                             bh[nt][0], bh[nt][1]);
                    mma_bf16(acc[mt][nt], ah[mt][0], ah[mt][1], ah[mt][2], ah[mt][3],
                             bl[nt][0], bl[nt][1]);
                }
        }
        if (ch + 1 < NCH) store_smem(buf ^ 1);
        __syncthreads();
    }

    // ---- epilogue ----
#pragma unroll
    for (int mt = 0; mt < 2; mt++) {
#pragma unroll
        for (int nt = 0; nt < 4; nt++) {
            int row = m0 + wm * 32 + mt * 16 + g;
            int col = n0 + wn * 32 + nt * 8 + tig * 2;
            if (col >= NCOLS) continue;
            float* cc = acc[mt][nt];
#pragma unroll
            for (int h = 0; h < 2; h++) {
                int r = row + h * 8;
                float v0 = cc[h * 2], v1 = cc[h * 2 + 1];
                if (MODE == 3) {
                    v0 += bias[col]; v1 += bias[col + 1];
                } else if (MODE == 2) {
                    int bi = r >> 11;  // Nn = 2048
                    float gp0 = g_gp[(size_t)r * HH + col];
                    float gp1 = g_gp[(size_t)r * HH + col + 1];
                    float gg0 = 1.f / (1.f + expf(-(v0 + g_cvec[bi * HH + col])));
                    float gg1 = 1.f / (1.f + expf(-(v1 + g_cvec[bi * HH + col + 1])));
                    v0 = gg0 * gp0 + (1.f - gg0) * g_att[bi * HH + col];
                    v1 = gg1 * gp1 + (1.f - gg1) * g_att[bi * HH + col + 1];
                }
                *(float2*)&C[(size_t)r * NCOLS + col] = make_float2(v0, v1);
            }
        }
    }
}

// ---------------- launcher (two-stream forked DAG) ----------------
extern "C" void kernel_launch(void* const* d_in, const int* in_sizes, int n_in,
                              void* d_out, int out_size) {
    const float* x      = (const float*)d_in[0];
    const float* text   = (const float*)d_in[1];
    const float* W      = (const float*)d_in[2];
    const float* bvec   = (const float*)d_in[3];
    const float* gate_w = (const float*)d_in[4];
    const float* gate_b = (const float*)d_in[5];
    const float* gnn_w  = (const float*)d_in[6];
    const float* gnn_b  = (const float*)d_in[7];
    const float* text_w = (const float*)d_in[8];
    const float* text_b = (const float*)d_in[9];
    const float* in_w   = (const float*)d_in[10];
    const float* in_b   = (const float*)d_in[11];
    const float* aow    = (const float*)d_in[12];
    const float* aob    = (const float*)d_in[13];
    const float* fgw    = (const float*)d_in[14];
    const float* fgb    = (const float*)d_in[15];
    const float* outp_w = (const float*)d_in[16];
    const float* outp_b = (const float*)d_in[17];
    const int*   en     = (const int*)d_in[18];
    float* outp = (float*)d_out;

    static cudaStream_t s2 = nullptr;
    static cudaEvent_t evFork, evEdgeA, evSide, evConst;
    static bool once = false;
    if (!once) {
        cudaFuncSetAttribute(tgemm<1>, cudaFuncAttributeMaxDynamicSharedMemorySize, SMEM_BYTES);
        cudaFuncSetAttribute(tgemm<2>, cudaFuncAttributeMaxDynamicSharedMemorySize, SMEM_BYTES);
        cudaFuncSetAttribute(tgemm<3>, cudaFuncAttributeMaxDynamicSharedMemorySize, SMEM_BYTES);
        cudaStreamCreateWithFlags(&s2, cudaStreamNonBlocking);
        cudaEventCreateWithFlags(&evFork,  cudaEventDisableTiming);
        cudaEventCreateWithFlags(&evEdgeA, cudaEventDisableTiming);
        cudaEventCreateWithFlags(&evSide,  cudaEventDisableTiming);
        cudaEventCreateWithFlags(&evConst, cudaEventDisableTiming);
        once = true;
    }

    // ---- fork side stream off the (captured) main stream ----
    cudaEventRecord(evFork, 0);
    cudaStreamWaitEvent(s2, evFork, 0);

    // ---- side chain (hidden under main-path GEMMs) ----
    k_init<<<256, 256, 0, s2>>>(x, gate_w);
    k_edge_a<<<EE * DEG / 256, 256, 0, s2>>>(en);
    cudaEventRecord(evEdgeA, s2);
    k_sort<<<NN / 64, 64, 0, s2>>>();
    k_alpha_fin<<<1, 256, 0, s2>>>(gate_b);
    cudaEventRecord(evSide, s2);
    k_const<<<BB, 128, 0, s2>>>(text, text_w, text_b, in_w, in_b, aow, aob, fgw, fgb);
    cudaEventRecord(evConst, s2);

    // ---- main (critical) chain ----
    k_prec<<<13, 256>>>(W, gnn_w, gnn_b, bvec);

    // y = x @ Wg  (tensor)
    tgemm<1><<<dim3(2, 64), 256, SMEM_BYTES>>>(x, nullptr, nullptr, nullptr);

    // sparse propagation on y (128 cols)
    cudaStreamWaitEvent(0, evEdgeA, 0);
    k_edge_b<<<EE / 4, 128>>>(en);
    cudaStreamWaitEvent(0, evSide, 0);
    k_gather<<<NN / 8, 256>>>();

    // fused = sigmoid(gp @ fgate_w0 + c[b]) * gp + (1-g) * att[b]
    cudaStreamWaitEvent(0, evConst, 0);
    tgemm<2><<<dim3(2, 64), 256, SMEM_BYTES>>>(nullptr, fgw, nullptr, nullptr);

    // result = fused @ outp_w + outp_b
    tgemm<3><<<dim3(4, 64), 256, SMEM_BYTES>>>(nullptr, outp_w, outp, outp_b);
}

// round 12
// speedup vs baseline: 1.1683x; 1.1683x over previous
#include <cuda_runtime.h>
#include <cuda_bf16.h>
#include <math.h>
#include <stdint.h>

#define NN   8192
#define DD   200
#define BB   4
#define EE   4096
#define DEG  16
#define HH   128
#define EPSf 1e-8f
#define MAXDEG 64

// ---------------- scratch (device globals; no allocation allowed) ----------------
__device__ float g_y[NN * HH];        // x @ Wg
__device__ float g_Medge[EE * HH];
__device__ float g_gp[NN * HH];
__device__ float g_fused[NN * HH];
__device__ float g_Wg[DD * HH];       // W @ gnn_w
__device__ float g_bg[HH];            // b @ gnn_w + gnn_b
__device__ int   g_dv_cnt[NN];        // degree AND list cursor
__device__ int   g_de_cnt[EE];
__device__ unsigned g_maskbits[EE];
__device__ int   g_node_edges[NN * MAXDEG];
__device__ float g_alpha_part[256];
__device__ float g_alpha;
__device__ float g_att[BB * HH];
__device__ float g_cvec[BB * HH];

// ---------------- init: zero degree counters + alpha partial sums ----------------
__global__ void k_init(const float* __restrict__ x, const float* __restrict__ gw) {
    __shared__ float sm[256];
    int t = threadIdx.x;
    int gi = blockIdx.x * 256 + t;
    if (gi < NN) g_dv_cnt[gi] = 0;
    float s = 0.f;
    for (int i = gi; i < NN * DD; i += 256 * 256)
        s += x[i] * gw[i % DD];
    sm[t] = s; __syncthreads();
    for (int o = 128; o > 0; o >>= 1) { if (t < o) sm[t] += sm[t + o]; __syncthreads(); }
    if (t == 0) g_alpha_part[blockIdx.x] = sm[0];
}

// ---------------- edge pass: slot-parallel dedup + degree + list fill ----------------
// block 0 additionally finalizes alpha (g_alpha_part written by k_init, done by stream order)
__global__ void __launch_bounds__(256) k_edge_a(const int* __restrict__ en,
                                                const float* __restrict__ gb) {
    if (blockIdx.x == 0) {
        __shared__ float smf[256];
        int t = threadIdx.x;
        smf[t] = g_alpha_part[t]; __syncthreads();
        for (int o = 128; o > 0; o >>= 1) { if (t < o) smf[t] += smf[t + o]; __syncthreads(); }
        if (t == 0) g_alpha = 1.f / (1.f + expf(-(smf[0] / (float)NN + gb[0])));
    }
    const int gt   = blockIdx.x * 256 + threadIdx.x;   // 0 .. EE*DEG-1
    const int lane = threadIdx.x & 31;
    const int half = lane >> 4;
    const int s    = lane & 15;
    const int e    = (gt >> 5) * 2 + half;
    const int nd   = en[e * DEG + s];
    bool first = true;
#pragma unroll
    for (int j = 0; j < 15; j++) {
        int v = __shfl_sync(0xFFFFFFFFu, nd, (half << 4) + j);
        if (j < s && v == nd) first = false;
    }
    unsigned bal = __ballot_sync(0xFFFFFFFFu, first);
    unsigned m = (bal >> (half * 16)) & 0xFFFFu;
    if (s == 0) { g_maskbits[e] = m; g_de_cnt[e] = __popc(m); }
    if (first) {
        int p = atomicAdd(&g_dv_cnt[nd], 1);
        if (p < MAXDEG) g_node_edges[nd * MAXDEG + p] = e;
    }
}

// ---------------- Wg = W @ gnn_w ; bg = b @ gnn_w + gnn_b ; + per-batch consts ----------------
// blocks 0..12: prec ; blocks 13..16: k_const for batch (blockIdx-13)
__global__ void __launch_bounds__(256) k_prec_const(
        const float* __restrict__ W, const float* __restrict__ gnn_w,
        const float* __restrict__ gnn_b, const float* __restrict__ bvec,
        const float* __restrict__ text,
        const float* __restrict__ text_w, const float* __restrict__ text_b,
        const float* __restrict__ in_w,   const float* __restrict__ in_b,
        const float* __restrict__ aow,    const float* __restrict__ aob,
        const float* __restrict__ fgw,    const float* __restrict__ fgb) {
    const int tid = threadIdx.x;
    if (blockIdx.x >= 13) {
        // ---- per-batch constants (128 active threads) ----
        __shared__ float tp[HH];
        __shared__ float vv[HH];
        __shared__ float at[HH];
        int b = blockIdx.x - 13;
        int j = tid;
        if (j < HH) {
            float s = text_b[j];
            for (int k = 0; k < DD; k++) s += text[b * DD + k] * text_w[k * HH + j];
            tp[j] = s;
        }
        __syncthreads();
        if (j < HH) {
            float s = in_b[2 * HH + j];
            for (int k = 0; k < HH; k++) s += tp[k] * in_w[k * 3 * HH + 2 * HH + j];
            vv[j] = s;
        }
        __syncthreads();
        if (j < HH) {
            float s = aob[j];
            for (int k = 0; k < HH; k++) s += vv[k] * aow[k * HH + j];
            at[j] = s;
            g_att[b * HH + j] = s;
        }
        __syncthreads();
        if (j < HH) {
            float s = fgb[j];
            for (int k = 0; k < HH; k++) s += at[k] * fgw[(HH + k) * HH + j];
            g_cvec[b * HH + j] = s;
        }
        return;
    }
    // ---- prec ----
    __shared__ float rowv[16][DD + 1];
    const int r0 = blockIdx.x * 16;
    const int col = tid & 127;
    const int rg  = tid >> 7;
    for (int i = tid; i < 16 * DD; i += 256) {
        int rr = i / DD, kk = i % DD;
        int row = r0 + rr;
        float v = 0.f;
        if (row < DD)        v = W[(size_t)row * DD + kk];
        else if (row == DD)  v = bvec[kk];
        rowv[rr][kk] = v;
    }
    __syncthreads();
    float s[8];
#pragma unroll
    for (int i = 0; i < 8; i++) s[i] = 0.f;
#pragma unroll 4
    for (int k = 0; k < DD; k++) {
        float w = gnn_w[k * HH + col];
#pragma unroll
        for (int i = 0; i < 8; i++) s[i] += rowv[rg * 8 + i][k] * w;
    }
#pragma unroll
    for (int i = 0; i < 8; i++) {
        int row = r0 + rg * 8 + i;
        if (row < DD)       g_Wg[row * HH + col] = s[i];
        else if (row == DD) g_bg[col] = s[i] + gnn_b[col];
    }
}

// sort each node's edge list for deterministic FP order
__global__ void k_sort() {
    int n = blockIdx.x * blockDim.x + threadIdx.x;
    if (n >= NN) return;
    int len = g_dv_cnt[n]; if (len > MAXDEG) len = MAXDEG;
    int* a = &g_node_edges[n * MAXDEG];
    for (int i = 1; i < len; i++) {
        int key = a[i]; int j = i - 1;
        while (j >= 0 && a[j] > key) { a[j + 1] = a[j]; j--; }
        a[j + 1] = key;
    }
}

// Medge[e,:] over y (128 cols); 4 edges/block, 32 lanes/edge
__global__ void __launch_bounds__(128) k_edge_b(const int* __restrict__ en) {
    __shared__ int   sn[4][DEG];
    __shared__ float sw[4][DEG];
    const int tid = threadIdx.x;
    const int sub = tid >> 5, lane = tid & 31;
    const int e0 = blockIdx.x * 4;
    if (tid < 64) {
        int ee = tid >> 4, s = tid & 15;
        int e = e0 + ee;
        int n = en[e * DEG + s];
        sn[ee][s] = n;
        sw[ee][s] = ((g_maskbits[e] >> s) & 1u)
                      ? rsqrtf((float)g_dv_cnt[n] * (1.f / DEG) + EPSf) : 0.f;
    }
    __syncthreads();
    const int e = e0 + sub;
    float4 acc = make_float4(0.f, 0.f, 0.f, 0.f);
#pragma unroll
    for (int s = 0; s < DEG; s++) {
        float w = sw[sub][s];
        float4 v = ((const float4*)&g_y[(size_t)sn[sub][s] * HH])[lane];
        acc.x += w * v.x; acc.y += w * v.y; acc.z += w * v.z; acc.w += w * v.w;
    }
    float sc = 1.f / ((float)g_de_cnt[e] * (1.f / DEG) + EPSf) * (1.f / (DEG * DEG));
    ((float4*)&g_Medge[(size_t)e * HH])[lane] =
        make_float4(acc.x * sc, acc.y * sc, acc.z * sc, acc.w * sc);
}

// gp = alpha*y + (1-alpha)*dv*sum Medge + bg ; 8 nodes/block (warp per node)
__global__ void __launch_bounds__(256) k_gather() {
    const int n = blockIdx.x * 8 + (threadIdx.x >> 5);
    const int lane = threadIdx.x & 31;
    int len  = g_dv_cnt[n]; if (len > MAXDEG) len = MAXDEG;
    const int base = n * MAXDEG;
    const float dvn = rsqrtf((float)g_dv_cnt[n] * (1.f / DEG) + EPSf);
    const float alpha = g_alpha, beta = 1.f - alpha;
    float4 acc = make_float4(0.f, 0.f, 0.f, 0.f);
    for (int i = 0; i < len; i++) {
        int e = g_node_edges[base + i];
        float4 v = ((const float4*)&g_Medge[(size_t)e * HH])[lane];
        acc.x += v.x; acc.y += v.y; acc.z += v.z; acc.w += v.w;
    }
    float4 yv = ((const float4*)&g_y[(size_t)n * HH])[lane];
    float4 bg = ((const float4*)g_bg)[lane];
    ((float4*)&g_gp[(size_t)n * HH])[lane] =
        make_float4(alpha * yv.x + beta * dvn * acc.x + bg.x,
                    alpha * yv.y + beta * dvn * acc.y + bg.y,
                    alpha * yv.z + beta * dvn * acc.z + bg.z,
                    alpha * yv.w + beta * dvn * acc.w + bg.w);
}

// ---------------- tensor-core GEMM: double-buffered, packed hi/lo smem ----------------
__device__ __forceinline__ void mma_bf16(float* c, uint32_t a0, uint32_t a1,
                                         uint32_t a2, uint32_t a3,
                                         uint32_t b0, uint32_t b1) {
    asm volatile("mma.sync.aligned.m16n8k16.row.col.f32.bf16.bf16.f32 "
        "{%0,%1,%2,%3}, {%4,%5,%6,%7}, {%8,%9}, {%0,%1,%2,%3};"
        : "+f"(c[0]), "+f"(c[1]), "+f"(c[2]), "+f"(c[3])
        : "r"(a0), "r"(a1), "r"(a2), "r"(a3), "r"(b0), "r"(b1));
}
__device__ __forceinline__ void split2(float v0, float v1, uint32_t& hi, uint32_t& lo) {
    __nv_bfloat16 h0 = __float2bfloat16(v0), h1 = __float2bfloat16(v1);
    float l0 = v0 - __bfloat162float(h0);
    float l1 = v1 - __bfloat162float(h1);
    hi = (uint32_t)__bfloat16_as_ushort(h0) | ((uint32_t)__bfloat16_as_ushort(h1) << 16);
    lo = (uint32_t)__bfloat16_as_ushort(__float2bfloat16(l0))
       | ((uint32_t)__bfloat16_as_ushort(__float2bfloat16(l1)) << 16);
}

#define PST 40                 // u32 row stride
#define STG2 (192 * PST)       // u32 per stage
#define SMEM_BYTES (2 * STG2 * 4)

template <int MODE>
__global__ void __launch_bounds__(256)
tgemm(const float* __restrict__ Aext, const float* __restrict__ Bext,
      float* __restrict__ Cext, const float* __restrict__ bias) {
    constexpr int NCOLS = (MODE == 3) ? 200 : 128;
    constexpr int K     = (MODE == 1) ? 200 : 128;
    constexpr int LDA   = (MODE == 1) ? 200 : 128;
    constexpr int NCH   = (K + 31) / 32;

    extern __shared__ uint32_t sm[];

    const float* A = (MODE == 1) ? Aext
                   : (MODE == 2) ? (const float*)g_gp : (const float*)g_fused;
    const float* Bsrc = (MODE == 1) ? (const float*)g_Wg : Bext;
    float* C = (MODE == 1) ? (float*)g_y
             : (MODE == 2) ? (float*)g_fused : Cext;

    const int tid = threadIdx.x;
    const int lane = tid & 31;
    const int w = tid >> 5;
    const int wm = w & 3, wn = w >> 2;
    const int g = lane >> 2, tig = lane & 3;
    const int m0 = blockIdx.y * 128, n0 = blockIdx.x * 64;

    const int a_row = tid >> 3, a_kq = (tid & 7) * 4;
    const int b_m = tid & 15, b_nq = (tid >> 4) * 4;

    float acc[2][4][4];
#pragma unroll
    for (int mt = 0; mt < 2; mt++)
#pragma unroll
        for (int nt = 0; nt < 4; nt++)
#pragma unroll
            for (int j = 0; j < 4; j++) acc[mt][nt][j] = 0.f;

    const float4 z4 = make_float4(0.f, 0.f, 0.f, 0.f);
    float4 ar[4];
    float4 br0, br1;

    auto load_raw = [&](int k0) {
#pragma unroll
        for (int i = 0; i < 4; i++) {
            int row = a_row + i * 32;
            int gk = k0 + a_kq;
            ar[i] = (gk < K) ? *(const float4*)&A[(size_t)(m0 + row) * LDA + gk] : z4;
        }
        int gk0 = k0 + 2 * b_m, gk1 = gk0 + 1, gn = n0 + b_nq;
        br0 = (gk0 < K && gn < NCOLS) ? *(const float4*)&Bsrc[(size_t)gk0 * NCOLS + gn] : z4;
        br1 = (gk1 < K && gn < NCOLS) ? *(const float4*)&Bsrc[(size_t)gk1 * NCOLS + gn] : z4;
    };
    auto store_smem = [&](int buf) {
        uint32_t* Ap = sm + buf * STG2;
        uint32_t* Bp = Ap + 128 * PST;
#pragma unroll
        for (int i = 0; i < 4; i++) {
            int row = a_row + i * 32;
            uint32_t h0, l0, h1, l1;
            split2(ar[i].x, ar[i].y, h0, l0);
            split2(ar[i].z, ar[i].w, h1, l1);
            uint32_t* p = Ap + row * PST + a_kq;
            p[0] = h0; p[1] = l0; p[2] = h1; p[3] = l1;
        }
        float b0e[4] = {br0.x, br0.y, br0.z, br0.w};
        float b1e[4] = {br1.x, br1.y, br1.z, br1.w};
#pragma unroll
        for (int q = 0; q < 4; q++) {
            uint32_t hi, lo;
            split2(b0e[q], b1e[q], hi, lo);
            uint32_t* p = Bp + (b_nq + q) * PST + 2 * b_m;
            p[0] = hi; p[1] = lo;
        }
    };

    load_raw(0);
    store_smem(0);
    __syncthreads();

    for (int ch = 0; ch < NCH; ch++) {
        const int buf = ch & 1;
        const uint32_t* Ap = sm + buf * STG2;
        const uint32_t* Bp = Ap + 128 * PST;
        if (ch + 1 < NCH) load_raw((ch + 1) * 32);
#pragma unroll
        for (int ks = 0; ks < 32; ks += 16) {
            uint32_t ah[2][4], al[2][4];
#pragma unroll
            for (int mt = 0; mt < 2; mt++) {
                int r = wm * 32 + mt * 16 + g;
                uint2 p0 = *(const uint2*)(Ap + r * PST + ks + tig * 2);
                uint2 p1 = *(const uint2*)(Ap + (r + 8) * PST + ks + tig * 2);
                uint2 p2 = *(const uint2*)(Ap + r * PST + ks + tig * 2 + 8);
                uint2 p3 = *(const uint2*)(Ap + (r + 8) * PST + ks + tig * 2 + 8);
                ah[mt][0] = p0.x; al[mt][0] = p0.y;
                ah[mt][1] = p1.x; al[mt][1] = p1.y;
                ah[mt][2] = p2.x; al[mt][2] = p2.y;
                ah[mt][3] = p3.x; al[mt][3] = p3.y;
            }
            uint32_t bh[4][2], bl[4][2];
#pragma unroll
            for (int nt = 0; nt < 4; nt++) {
                int n = wn * 32 + nt * 8 + g;
                uint2 q0 = *(const uint2*)(Bp + n * PST + ks + tig * 2);
                uint2 q1 = *(const uint2*)(Bp + n * PST + ks + tig * 2 + 8);
                bh[nt][0] = q0.x; bl[nt][0] = q0.y;
                bh[nt][1] = q1.x; bl[nt][1] = q1.y;
            }
#pragma unroll
            for (int mt = 0; mt < 2; mt++)
#pragma unroll
                for (int nt = 0; nt < 4; nt++) {
                    mma_bf16(acc[mt][nt], ah[mt][0], ah[mt][1], ah[mt][2], ah[mt][3],
                             bh[nt][0], bh[nt][1]);
                    mma_bf16(acc[mt][nt], al[mt][0], al[mt][1], al[mt][2], al[mt][3],
                             bh[nt][0], bh[nt][1]);
                    mma_bf16(acc[mt][nt], ah[mt][0], ah[mt][1], ah[mt][2], ah[mt][3],
                             bl[nt][0], bl[nt][1]);
                }
        }
        if (ch + 1 < NCH) store_smem(buf ^ 1);
        __syncthreads();
    }

    // ---- epilogue ----
#pragma unroll
    for (int mt = 0; mt < 2; mt++) {
#pragma unroll
        for (int nt = 0; nt < 4; nt++) {
            int row = m0 + wm * 32 + mt * 16 + g;
            int col = n0 + wn * 32 + nt * 8 + tig * 2;
            if (col >= NCOLS) continue;
            float* cc = acc[mt][nt];
#pragma unroll
            for (int h = 0; h < 2; h++) {
                int r = row + h * 8;
                float v0 = cc[h * 2], v1 = cc[h * 2 + 1];
                if (MODE == 3) {
                    v0 += bias[col]; v1 += bias[col + 1];
                } else if (MODE == 2) {
                    int bi = r >> 11;  // Nn = 2048
                    float gp0 = g_gp[(size_t)r * HH + col];
                    float gp1 = g_gp[(size_t)r * HH + col + 1];
                    float gg0 = 1.f / (1.f + expf(-(v0 + g_cvec[bi * HH + col])));
                    float gg1 = 1.f / (1.f + expf(-(v1 + g_cvec[bi * HH + col + 1])));
                    v0 = gg0 * gp0 + (1.f - gg0) * g_att[bi * HH + col];
                    v1 = gg1 * gp1 + (1.f - gg1) * g_att[bi * HH + col + 1];
                }
                *(float2*)&C[(size_t)r * NCOLS + col] = make_float2(v0, v1);
            }
        }
    }
}

// ---------------- launcher (single stream, 9 nodes) ----------------
extern "C" void kernel_launch(void* const* d_in, const int* in_sizes, int n_in,
                              void* d_out, int out_size) {
    const float* x      = (const float*)d_in[0];
    const float* text   = (const float*)d_in[1];
    const float* W      = (const float*)d_in[2];
    const float* bvec   = (const float*)d_in[3];
    const float* gate_w = (const float*)d_in[4];
    const float* gate_b = (const float*)d_in[5];
    const float* gnn_w  = (const float*)d_in[6];
    const float* gnn_b  = (const float*)d_in[7];
    const float* text_w = (const float*)d_in[8];
    const float* text_b = (const float*)d_in[9];
    const float* in_w   = (const float*)d_in[10];
    const float* in_b   = (const float*)d_in[11];
    const float* aow    = (const float*)d_in[12];
    const float* aob    = (const float*)d_in[13];
    const float* fgw    = (const float*)d_in[14];
    const float* fgb    = (const float*)d_in[15];
    const float* outp_w = (const float*)d_in[16];
    const float* outp_b = (const float*)d_in[17];
    const int*   en     = (const int*)d_in[18];
    float* outp = (float*)d_out;

    static bool once = false;
    if (!once) {
        cudaFuncSetAttribute(tgemm<1>, cudaFuncAttributeMaxDynamicSharedMemorySize, SMEM_BYTES);
        cudaFuncSetAttribute(tgemm<2>, cudaFuncAttributeMaxDynamicSharedMemorySize, SMEM_BYTES);
        cudaFuncSetAttribute(tgemm<3>, cudaFuncAttributeMaxDynamicSharedMemorySize, SMEM_BYTES);
        once = true;
    }

    k_init<<<256, 256>>>(x, gate_w);

    // edge build (+ alpha finalize in block 0) ; sort
    k_edge_a<<<EE * DEG / 256, 256>>>(en, gate_b);
    k_sort<<<NN / 64, 64>>>();

    // Wg/bg precompute + per-batch attention constants (one wave)
    k_prec_const<<<17, 256>>>(W, gnn_w, gnn_b, bvec,
                              text, text_w, text_b, in_w, in_b, aow, aob, fgw, fgb);

    // y = x @ Wg  (tensor)
    tgemm<1><<<dim3(2, 64), 256, SMEM_BYTES>>>(x, nullptr, nullptr, nullptr);

    // sparse propagation on y (128 cols), gather writes gp directly
    k_edge_b<<<EE / 4, 128>>>(en);
    k_gather<<<NN / 8, 256>>>();

    // fused = sigmoid(gp @ fgate_w0 + c[b]) * gp + (1-g) * att[b]
    tgemm<2><<<dim3(2, 64), 256, SMEM_BYTES>>>(nullptr, fgw, nullptr, nullptr);

    // result = fused @ outp_w + outp_b
    tgemm<3><<<dim3(4, 64), 256, SMEM_BYTES>>>(nullptr, outp_w, outp, outp_b);
}